// round 16
// baseline (speedup 1.0000x reference)
#include <cuda_runtime.h>
#include <cuda_fp16.h>
#include <math.h>
#include <stdint.h>

// Problem constants
#define NTOK 8192
#define D_   1024
#define E_   8
#define FF_  4096
#define K_   2
#define NP   (NTOK * K_)            // 16384
#define TILE 128
#define PADROWS (NP + E_ * TILE)    // 17408
#define NTILES  (PADROWS / TILE)    // 136
#define KC 64                        // K halves per chunk (128B rows)
#define RSB 144                      // smem row stride bytes (128 data + 16 pad)
#define TILE_B (128 * RSB)           // 18432 B per 128-row tile
#define HTILE_B (64 * RSB)           // 9216 B per 64-row tile
#define STAGES 3
#define G1_STAGE_B (TILE_B + 2 * HTILE_B)   // 36864: A(128) + Bg(64) + Bu(64)
#define G1_SMEM (STAGES * G1_STAGE_B)       // 110592
#define G2_STAGE_B (TILE_B + HTILE_B)       // 27648: A(128) + B(64)
#define G2_SMEM (STAGES * G2_STAGE_B)       // 82944
#define WCOUNT ((size_t)E_ * FF_ * D_)      // 33554432 elements per weight tensor

// ------------------------- device scratch ----------------------------------
__device__ __align__(16) __half g_Wg16[WCOUNT];
__device__ __align__(16) __half g_Wu16[WCOUNT];
__device__ __align__(16) __half g_Wd16[WCOUNT];
__device__ __align__(16) __half g_H16[(size_t)PADROWS * FF_];
__device__ __align__(16) __half g_Xg16[(size_t)PADROWS * D_];
__device__ __align__(16) __half g_O16[(size_t)PADROWS * D_];
__device__ int   g_topk_idx[NP];
__device__ float g_topk_w[NP];
__device__ float g_probsum[E_];
__device__ int   g_count[E_];
__device__ float g_lse2;
__device__ int   g_offset[E_ + 1];
__device__ int   g_cursor[E_];
__device__ int   g_pair_token[PADROWS];
__device__ int   g_token_pos[NP];
__device__ int   g_tile_expert[NTILES];

// ------------------------- helpers -----------------------------------------
__device__ __forceinline__ uint32_t smem_u32(const void* p) {
    uint32_t a;
    asm("{ .reg .u64 t; cvta.to.shared.u64 t, %1; cvt.u32.u64 %0, t; }"
        : "=r"(a) : "l"(p));
    return a;
}
__device__ __forceinline__ void cp_async16(uint32_t s, const void* g) {
    asm volatile("cp.async.cg.shared.global [%0], [%1], 16;" :: "r"(s), "l"(g));
}
#define CP_COMMIT() asm volatile("cp.async.commit_group;" ::: "memory")
#define CP_WAIT(n)  asm volatile("cp.async.wait_group %0;" :: "n"(n) : "memory")

// D += A(16x16) * B(16x8)  fp16 in, fp32 accum
__device__ __forceinline__ void mma16(float* c, const uint32_t* a, uint32_t b0, uint32_t b1) {
    asm volatile(
        "mma.sync.aligned.m16n8k16.row.col.f32.f16.f16.f32 "
        "{%0,%1,%2,%3}, {%4,%5,%6,%7}, {%8,%9}, {%0,%1,%2,%3};"
        : "+f"(c[0]), "+f"(c[1]), "+f"(c[2]), "+f"(c[3])
        : "r"(a[0]), "r"(a[1]), "r"(a[2]), "r"(a[3]), "r"(b0), "r"(b1));
}

// ------------------------- init ---------------------------------------------
__global__ void init_kernel() {
    int i = blockIdx.x * blockDim.x + threadIdx.x;
    if (i < PADROWS) g_pair_token[i] = -1;
    if (i < E_) { g_count[i] = 0; g_probsum[i] = 0.f; g_cursor[i] = 0; }
    if (i == 0) g_lse2 = 0.f;
}

// ------------------------- fp32 -> fp16 conversions --------------------------
__global__ void convert_gu_kernel(const float* __restrict__ wg,
                                  const float* __restrict__ wu) {
    const size_t n4 = WCOUNT / 4;
    size_t stride = (size_t)gridDim.x * blockDim.x;
    for (size_t i = blockIdx.x * blockDim.x + threadIdx.x; i < 2 * n4; i += stride) {
        const float* src; __half* dst; size_t j;
        if (i < n4) { src = wg; dst = g_Wg16; j = i; }
        else        { src = wu; dst = g_Wu16; j = i - n4; }
        float4 v = __ldcs((const float4*)(src + j * 4));
        __half2 p0 = __floats2half2_rn(v.x, v.y);
        __half2 p1 = __floats2half2_rn(v.z, v.w);
        uint2 u;
        u.x = *(uint32_t*)&p0;
        u.y = *(uint32_t*)&p1;
        *(uint2*)(dst + j * 4) = u;
    }
}
__global__ void convert_d_kernel(const float* __restrict__ wd) {
    const size_t n4 = WCOUNT / 4;
    size_t stride = (size_t)gridDim.x * blockDim.x;
    for (size_t i = blockIdx.x * blockDim.x + threadIdx.x; i < n4; i += stride) {
        float4 v = __ldcs((const float4*)(wd + i * 4));
        __half2 p0 = __floats2half2_rn(v.x, v.y);
        __half2 p1 = __floats2half2_rn(v.z, v.w);
        uint2 u;
        u.x = *(uint32_t*)&p0;
        u.y = *(uint32_t*)&p1;
        *(uint2*)(g_Wd16 + i * 4) = u;
    }
}

// ------------------------- router (fp32, smem-cached gate_W) -----------------
__global__ __launch_bounds__(256) void router_kernel(const float* __restrict__ x,
                                                     const float* __restrict__ gw) {
    __shared__ float4 s_gw[E_ * 256];     // 32KB
    __shared__ float s_p[E_];
    __shared__ int   s_c[E_];
    __shared__ float s_l;
    const int tid = threadIdx.x;
    if (tid < E_) { s_p[tid] = 0.f; s_c[tid] = 0; }
    if (tid == 0) s_l = 0.f;
    for (int i = tid; i < E_ * 256; i += 256) s_gw[i] = ((const float4*)gw)[i];
    __syncthreads();

    int warp = (blockIdx.x * blockDim.x + tid) >> 5;
    int lane = tid & 31;
    {
        const float4* xr = (const float4*)(x + (size_t)warp * D_);
        float acc[E_];
#pragma unroll
        for (int e = 0; e < E_; e++) acc[e] = 0.f;
#pragma unroll
        for (int it = 0; it < 8; it++) {
            int i4 = lane + it * 32;
            float4 xv = xr[i4];
#pragma unroll
            for (int e = 0; e < E_; e++) {
                float4 w4 = s_gw[e * 256 + i4];
                acc[e] += xv.x * w4.x + xv.y * w4.y + xv.z * w4.z + xv.w * w4.w;
            }
        }
#pragma unroll
        for (int e = 0; e < E_; e++)
#pragma unroll
            for (int o = 16; o; o >>= 1)
                acc[e] += __shfl_xor_sync(0xffffffffu, acc[e], o);

        if (lane == 0) {
            float mx = acc[0];
#pragma unroll
            for (int e = 1; e < E_; e++) mx = fmaxf(mx, acc[e]);
            float p[E_], se = 0.f;
#pragma unroll
            for (int e = 0; e < E_; e++) { p[e] = expf(acc[e] - mx); se += p[e]; }
            float lse = mx + logf(se);
            float inv = 1.f / se;
#pragma unroll
            for (int e = 0; e < E_; e++) p[e] *= inv;

            int i1 = 0;
#pragma unroll
            for (int e = 1; e < E_; e++) if (p[e] > p[i1]) i1 = e;
            int i2 = (i1 == 0) ? 1 : 0;
#pragma unroll
            for (int e = 0; e < E_; e++) if (e != i1 && p[e] > p[i2]) i2 = e;

            float s2 = p[i1] + p[i2] + 1e-6f;
            g_topk_idx[2 * warp]     = i1;
            g_topk_w[2 * warp]       = p[i1] / s2;
            g_topk_idx[2 * warp + 1] = i2;
            g_topk_w[2 * warp + 1]   = p[i2] / s2;

            atomicAdd(&s_c[i1], 1);
            atomicAdd(&s_c[i2], 1);
#pragma unroll
            for (int e = 0; e < E_; e++) atomicAdd(&s_p[e], p[e]);
            atomicAdd(&s_l, lse * lse);
        }
    }
    __syncthreads();
    if (tid < E_) {
        atomicAdd(&g_probsum[tid], s_p[tid]);
        atomicAdd(&g_count[tid],   s_c[tid]);
    }
    if (tid == 0) atomicAdd(&g_lse2, s_l);
}

// ------------------------- scatter (+ inline scan / tile map / aux) ---------
__global__ void scatter_kernel(float* __restrict__ d_out, int out_size) {
    int offs[E_ + 1];
    int off = 0;
#pragma unroll
    for (int e = 0; e < E_; e++) {
        offs[e] = off;
        off += ((g_count[e] + TILE - 1) / TILE) * TILE;
    }
    offs[E_] = off;

    int i = blockIdx.x * blockDim.x + threadIdx.x;
    if (i < NP) {
        int e   = g_topk_idx[i];
        int pos = offs[e] + atomicAdd(&g_cursor[e], 1);
        g_pair_token[pos] = i >> 1;
        g_token_pos[i]    = pos;
    }

    if (blockIdx.x == 0) {
        int t = threadIdx.x;
        if (t <= E_) g_offset[t] = offs[t];
        if (t < NTILES) {
            int r = t * TILE;
            int e = E_ - 1;
#pragma unroll
            for (int j = 0; j < E_; j++)
                if (r < offs[j + 1]) { e = j; break; }
            g_tile_expert[t] = e;
        }
        if (t == 0) {
            float lb = 0.f;
#pragma unroll
            for (int e = 0; e < E_; e++)
                lb += ((float)g_count[e] / (float)NP) * (g_probsum[e] / (float)NTOK);
            lb *= (float)E_;
            float z   = (g_lse2 / (float)NTOK) * 1e-3f;
            float aux = 0.01f * (lb + z);
            if (out_size > NTOK * D_) d_out[NTOK * D_] = aux;
        }
    }
}

// ------------------------- gather x rows -> fp16 ----------------------------
__global__ void gather_kernel(const float* __restrict__ x) {
    int r = blockIdx.x;
    if (r >= g_offset[E_]) return;
    int tok = g_pair_token[r];
    uint2 u = make_uint2(0u, 0u);
    if (tok >= 0) {
        float4 v = *(const float4*)(x + (size_t)tok * D_ + threadIdx.x * 4);
        __half2 p0 = __floats2half2_rn(v.x, v.y);
        __half2 p1 = __floats2half2_rn(v.z, v.w);
        u.x = *(uint32_t*)&p0;
        u.y = *(uint32_t*)&p1;
    }
    *(uint2*)(g_Xg16 + (size_t)r * D_ + threadIdx.x * 4) = u;
}

// ------------------------- GEMM1: H = silu(X Wg^T) * (X Wu^T) ---------------
// Single-pass fused, block tile 128(M)x64(N) over BOTH gate and up.
// 256 threads, warp tile 64(M)x16(N) per tensor, 3-stage cp.async, occ 2.
__global__ __launch_bounds__(256, 2) void gemm1_kernel() {
    if ((int)blockIdx.y * 128 >= g_offset[E_]) return;   // skip empty tiles
    extern __shared__ __align__(16) char smc[];
    const uint32_t smb = smem_u32(smc);
    const int tid = threadIdx.x, wid = tid >> 5, lane = tid & 31;
    const int wm = wid & 1, wn = wid >> 1;               // 2 x 4 warps
    const int gq = lane >> 2, tq = lane & 3;
    const int bx = blockIdx.x, by = blockIdx.y;          // bx: 64-col tile of FF
    const int e = g_tile_expert[by];
    const __half* A0  = g_Xg16 + (size_t)by * 128 * D_;
    const __half* Bg0 = g_Wg16 + (size_t)e * FF_ * D_ + (size_t)bx * 64 * D_;
    const __half* Bu0 = g_Wu16 + (size_t)e * FF_ * D_ + (size_t)bx * 64 * D_;

    float cg[4][2][4], cu[4][2][4];
#pragma unroll
    for (int m = 0; m < 4; m++)
#pragma unroll
        for (int j = 0; j < 2; j++)
#pragma unroll
            for (int q = 0; q < 4; q++) { cg[m][j][q] = 0.f; cu[m][j][q] = 0.f; }

    const int C = D_ / KC;   // 16

#define G1_LOAD(c_)                                                            \
    do {                                                                       \
        uint32_t sb_ = smb + ((c_) % STAGES) * G1_STAGE_B;                     \
        const __half* a_  = A0  + (c_) * KC;                                   \
        const __half* bg_ = Bg0 + (c_) * KC;                                   \
        const __half* bu_ = Bu0 + (c_) * KC;                                   \
        _Pragma("unroll")                                                      \
        for (int i_ = 0; i_ < 4; i_++) {           /* A: 128 rows */           \
            int idx_ = i_ * 256 + tid;                                         \
            int r_ = idx_ >> 3, ch_ = idx_ & 7;                                \
            uint32_t off_ = (uint32_t)(r_ * RSB + ch_ * 16);                   \
            cp_async16(sb_ + off_, a_ + (size_t)r_ * D_ + ch_ * 8);            \
        }                                                                      \
        _Pragma("unroll")                                                      \
        for (int i_ = 0; i_ < 2; i_++) {           /* Bg/Bu: 64 rows */        \
            int idx_ = i_ * 256 + tid;                                         \
            int r_ = idx_ >> 3, ch_ = idx_ & 7;                                \
            uint32_t off_ = (uint32_t)(r_ * RSB + ch_ * 16);                   \
            cp_async16(sb_ + TILE_B + off_,                                    \
                       bg_ + (size_t)r_ * D_ + ch_ * 8);                       \
            cp_async16(sb_ + TILE_B + HTILE_B + off_,                          \
                       bu_ + (size_t)r_ * D_ + ch_ * 8);                       \
        }                                                                      \
        CP_COMMIT();                                                           \
    } while (0)

    G1_LOAD(0);
    G1_LOAD(1);

    for (int c = 0; c < C; c++) {
        if (c + 2 < C) CP_WAIT(1); else CP_WAIT(0);
        __syncthreads();
        if (c + 2 < C) G1_LOAD(c + 2);

        const char* As = smc + (c % STAGES) * G1_STAGE_B;
        const char* Gs = As + TILE_B;
        const char* Us = Gs + HTILE_B;
#pragma unroll
        for (int ks = 0; ks < 4; ks++) {
            const int kb = ks * 32;
            uint32_t a[4][4];
#pragma unroll
            for (int m = 0; m < 4; m++) {
                int r0 = wm * 64 + m * 16 + gq;
                a[m][0] = *(const uint32_t*)(As + r0 * RSB + kb + 4 * tq);
                a[m][1] = *(const uint32_t*)(As + (r0 + 8) * RSB + kb + 4 * tq);
                a[m][2] = *(const uint32_t*)(As + r0 * RSB + kb + 16 + 4 * tq);
                a[m][3] = *(const uint32_t*)(As + (r0 + 8) * RSB + kb + 16 + 4 * tq);
            }
#pragma unroll
            for (int j = 0; j < 2; j++) {
                int n = wn * 16 + j * 8 + gq;
                uint32_t g0 = *(const uint32_t*)(Gs + n * RSB + kb + 4 * tq);
                uint32_t g1 = *(const uint32_t*)(Gs + n * RSB + kb + 16 + 4 * tq);
#pragma unroll
                for (int m = 0; m < 4; m++) mma16(cg[m][j], a[m], g0, g1);
                uint32_t u0 = *(const uint32_t*)(Us + n * RSB + kb + 4 * tq);
                uint32_t u1 = *(const uint32_t*)(Us + n * RSB + kb + 16 + 4 * tq);
#pragma unroll
                for (int m = 0; m < 4; m++) mma16(cu[m][j], a[m], u0, u1);
            }
        }
    }

    // epilogue: h = silu(g) * u  (fp32, fused) -> fp16 H
#pragma unroll
    for (int m = 0; m < 4; m++) {
        int row = by * 128 + wm * 64 + m * 16 + gq;
#pragma unroll
        for (int j = 0; j < 2; j++) {
            int col = bx * 64 + wn * 16 + j * 8 + 2 * tq;
            float gg0 = cg[m][j][0], gg1 = cg[m][j][1];
            float gg2 = cg[m][j][2], gg3 = cg[m][j][3];
            float h0 = gg0 / (1.f + __expf(-gg0)) * cu[m][j][0];
            float h1 = gg1 / (1.f + __expf(-gg1)) * cu[m][j][1];
            float h2 = gg2 / (1.f + __expf(-gg2)) * cu[m][j][2];
            float h3 = gg3 / (1.f + __expf(-gg3)) * cu[m][j][3];
            *(__half2*)&g_H16[(size_t)row * FF_ + col]       = __floats2half2_rn(h0, h1);
            *(__half2*)&g_H16[(size_t)(row + 8) * FF_ + col] = __floats2half2_rn(h2, h3);
        }
    }
}

// ------------------------- GEMM2: O = H Wd^T (fp16 out) ---------------------
// Block tile 128(M)x64(N), 58us blocks shorten the end-of-kernel straggler.
// 256 threads, warp tile 64(M)x16(N), 3-stage cp.async, occ 2.
__global__ __launch_bounds__(256, 2) void gemm2_kernel() {
    if ((int)blockIdx.y * 128 >= g_offset[E_]) return;   // skip empty tiles
    extern __shared__ __align__(16) char smc[];
    const uint32_t smb = smem_u32(smc);
    const int tid = threadIdx.x, wid = tid >> 5, lane = tid & 31;
    const int wm = wid & 1, wn = wid >> 1;
    const int gq = lane >> 2, tq = lane & 3;
    const int bx = blockIdx.x, by = blockIdx.y;          // bx: 64-col tile of D
    const int e = g_tile_expert[by];
    const __half* A0 = g_H16 + (size_t)by * 128 * FF_;
    const __half* B0 = g_Wd16 + (size_t)e * D_ * FF_ + (size_t)bx * 64 * FF_;

    float cc[4][2][4];
#pragma unroll
    for (int m = 0; m < 4; m++)
#pragma unroll
        for (int j = 0; j < 2; j++)
#pragma unroll
            for (int q = 0; q < 4; q++) cc[m][j][q] = 0.f;

    const int C = FF_ / KC;   // 64

#define G2_LOAD(c_)                                                            \
    do {                                                                       \
        uint32_t sb_ = smb + ((c_) % STAGES) * G2_STAGE_B;                     \
        const __half* a_ = A0 + (c_) * KC;                                     \
        const __half* b_ = B0 + (c_) * KC;                                     \
        _Pragma("unroll")                                                      \
        for (int i_ = 0; i_ < 4; i_++) {           /* A: 128 rows */           \
            int idx_ = i_ * 256 + tid;                                         \
            int r_ = idx_ >> 3, ch_ = idx_ & 7;                                \
            uint32_t off_ = (uint32_t)(r_ * RSB + ch_ * 16);                   \
            cp_async16(sb_ + off_, a_ + (size_t)r_ * FF_ + ch_ * 8);           \
        }                                                                      \
        _Pragma("unroll")                                                      \
        for (int i_ = 0; i_ < 2; i_++) {           /* B: 64 rows */            \
            int idx_ = i_ * 256 + tid;                                         \
            int r_ = idx_ >> 3, ch_ = idx_ & 7;                                \
            uint32_t off_ = (uint32_t)(r_ * RSB + ch_ * 16);                   \
            cp_async16(sb_ + TILE_B + off_, b_ + (size_t)r_ * FF_ + ch_ * 8);  \
        }                                                                      \
        CP_COMMIT();                                                           \
    } while (0)

    G2_LOAD(0);
    G2_LOAD(1);

    for (int c = 0; c < C; c++) {
        if (c + 2 < C) CP_WAIT(1); else CP_WAIT(0);
        __syncthreads();
        if (c + 2 < C) G2_LOAD(c + 2);

        const char* As = smc + (c % STAGES) * G2_STAGE_B;
        const char* Bs = As + TILE_B;
#pragma unroll
        for (int ks = 0; ks < 4; ks++) {
            const int kb = ks * 32;
            uint32_t a[4][4];
#pragma unroll
            for (int m = 0; m < 4; m++) {
                int r0 = wm * 64 + m * 16 + gq;
                a[m][0] = *(const uint32_t*)(As + r0 * RSB + kb + 4 * tq);
                a[m][1] = *(const uint32_t*)(As + (r0 + 8) * RSB + kb + 4 * tq);
                a[m][2] = *(const uint32_t*)(As + r0 * RSB + kb + 16 + 4 * tq);
                a[m][3] = *(const uint32_t*)(As + (r0 + 8) * RSB + kb + 16 + 4 * tq);
            }
#pragma unroll
            for (int j = 0; j < 2; j++) {
                int n = wn * 16 + j * 8 + gq;
                uint32_t b0 = *(const uint32_t*)(Bs + n * RSB + kb + 4 * tq);
                uint32_t b1 = *(const uint32_t*)(Bs + n * RSB + kb + 16 + 4 * tq);
#pragma unroll
                for (int m = 0; m < 4; m++) mma16(cc[m][j], a[m], b0, b1);
            }
        }
    }

#pragma unroll
    for (int m = 0; m < 4; m++) {
        int row = by * 128 + wm * 64 + m * 16 + gq;
#pragma unroll
        for (int j = 0; j < 2; j++) {
            int col = bx * 64 + wn * 16 + j * 8 + 2 * tq;
            *(__half2*)&g_O16[(size_t)row * D_ + col] =
                __floats2half2_rn(cc[m][j][0], cc[m][j][1]);
            *(__half2*)&g_O16[(size_t)(row + 8) * D_ + col] =
                __floats2half2_rn(cc[m][j][2], cc[m][j][3]);
        }
    }
}

// ------------------------- combine + residual + LayerNorm -------------------
__global__ void combine_ln_kernel(const float* __restrict__ x,
                                  const float* __restrict__ gamma,
                                  const float* __restrict__ beta,
                                  float* __restrict__ out) {
    int t  = blockIdx.x;
    int p0 = g_token_pos[2 * t];
    int p1 = g_token_pos[2 * t + 1];
    float w0 = g_topk_w[2 * t];
    float w1 = g_topk_w[2 * t + 1];
    const float*  xr = x     + (size_t)t  * D_;
    const __half* o0 = g_O16 + (size_t)p0 * D_;
    const __half* o1 = g_O16 + (size_t)p1 * D_;

    int d4 = threadIdx.x * 4;
    float4 xv = *(const float4*)(xr + d4);
    uint2 u0 = *(const uint2*)(o0 + d4);
    uint2 u1 = *(const uint2*)(o1 + d4);
    __half2 a0 = *(__half2*)&u0.x, a1 = *(__half2*)&u0.y;
    __half2 b0 = *(__half2*)&u1.x, b1 = *(__half2*)&u1.y;

    float v[4];
    v[0] = xv.x + w0 * __low2float(a0)  + w1 * __low2float(b0);
    v[1] = xv.y + w0 * __high2float(a0) + w1 * __high2float(b0);
    v[2] = xv.z + w0 * __low2float(a1)  + w1 * __low2float(b1);
    v[3] = xv.w + w0 * __high2float(a1) + w1 * __high2float(b1);

    float s = v[0] + v[1] + v[2] + v[3];
    float s2 = v[0] * v[0] + v[1] * v[1] + v[2] * v[2] + v[3] * v[3];
#pragma unroll
    for (int o = 16; o; o >>= 1) {
        s  += __shfl_xor_sync(0xffffffffu, s, o);
        s2 += __shfl_xor_sync(0xffffffffu, s2, o);
    }
    __shared__ float rs[8], rs2[8];
    __shared__ float s_mu, s_rstd;
    int wid = threadIdx.x >> 5, lane = threadIdx.x & 31;
    if (lane == 0) { rs[wid] = s; rs2[wid] = s2; }
    __syncthreads();
    if (threadIdx.x == 0) {
        float S = 0.f, S2 = 0.f;
#pragma unroll
        for (int w = 0; w < 8; w++) { S += rs[w]; S2 += rs2[w]; }
        float mu  = S / (float)D_;
        float var = S2 / (float)D_ - mu * mu;
        s_mu   = mu;
        s_rstd = rsqrtf(var + 1e-5f);
    }
    __syncthreads();
    float mu = s_mu, rstd = s_rstd;
    float4 gv = *(const float4*)(gamma + d4);
    float4 bv = *(const float4*)(beta + d4);
    float4 ov;
    ov.x = (v[0] - mu) * rstd * gv.x + bv.x;
    ov.y = (v[1] - mu) * rstd * gv.y + bv.y;
    ov.z = (v[2] - mu) * rstd * gv.z + bv.z;
    ov.w = (v[3] - mu) * rstd * gv.w + bv.w;
    *(float4*)(out + (size_t)t * D_ + d4) = ov;
}

// ------------------------- launch -------------------------------------------
extern "C" void kernel_launch(void* const* d_in, const int* in_sizes, int n_in,
                              void* d_out, int out_size) {
    const float* x     = (const float*)d_in[0];
    const float* gateW = (const float*)d_in[1];
    const float* Wg    = (const float*)d_in[2];
    const float* Wu    = (const float*)d_in[3];
    const float* Wd    = (const float*)d_in[4];
    const float* gamma = (const float*)d_in[5];
    const float* beta  = (const float*)d_in[6];
    float* out = (float*)d_out;

    static cudaStream_t s2 = nullptr;
    static cudaEvent_t evA = nullptr, evGU = nullptr, evD = nullptr;
    if (!s2) {
        cudaStreamCreateWithFlags(&s2, cudaStreamNonBlocking);
        cudaEventCreateWithFlags(&evA,  cudaEventDisableTiming);
        cudaEventCreateWithFlags(&evGU, cudaEventDisableTiming);
        cudaEventCreateWithFlags(&evD,  cudaEventDisableTiming);
    }

    cudaFuncSetAttribute((const void*)gemm1_kernel,
                         cudaFuncAttributeMaxDynamicSharedMemorySize, G1_SMEM);
    cudaFuncSetAttribute((const void*)gemm2_kernel,
                         cudaFuncAttributeMaxDynamicSharedMemorySize, G2_SMEM);

    // Fork: weight conversion on s2 (gate+up first, then down).
    cudaEventRecord(evA, 0);
    cudaStreamWaitEvent(s2, evA, 0);
    convert_gu_kernel<<<4096, 256, 0, s2>>>(Wg, Wu);
    cudaEventRecord(evGU, s2);
    convert_d_kernel<<<4096, 256, 0, s2>>>(Wd);
    cudaEventRecord(evD, s2);

    // Routing pipeline on main stream.
    init_kernel<<<(PADROWS + 255) / 256, 256>>>();
    router_kernel<<<NTOK / 8, 256>>>(x, gateW);
    scatter_kernel<<<(NP + 255) / 256, 256>>>(out, out_size);
    gather_kernel<<<PADROWS, 256>>>(x);

    // GEMM1 needs only gate+up weights; GEMM2 also needs down weights.
    cudaStreamWaitEvent(0, evGU, 0);
    gemm1_kernel<<<dim3(FF_ / 64, NTILES), 256, G1_SMEM>>>();
    cudaStreamWaitEvent(0, evD, 0);
    gemm2_kernel<<<dim3(D_ / 64, NTILES), 256, G2_SMEM>>>();

    combine_ln_kernel<<<NTOK, 256>>>(x, gamma, beta, out);
}

// round 17
// speedup vs baseline: 1.1106x; 1.1106x over previous
#include <cuda_runtime.h>
#include <cuda_fp16.h>
#include <math.h>
#include <stdint.h>

// Problem constants
#define NTOK 8192
#define D_   1024
#define E_   8
#define FF_  4096
#define K_   2
#define NP   (NTOK * K_)            // 16384
#define TILE 128
#define PADROWS (NP + E_ * TILE)    // 17408
#define NTILES  (PADROWS / TILE)    // 136
#define KC 64                        // K halves per chunk (128B rows)
#define RSB 144                      // smem row stride bytes (128 data + 16 pad)
#define TILE_B (128 * RSB)           // 18432 B per 128-row tile
#define HTILE_B (64 * RSB)           // 9216 B per 64-row tile
#define STAGES 3
#define G1_STAGE_B (TILE_B + 2 * HTILE_B)   // 36864: A(128) + Bg(64) + Bu(64)
#define G1_SMEM (STAGES * G1_STAGE_B)       // 110592
#define G2_SMEM (STAGES * 2 * TILE_B)       // 110592
#define WCOUNT ((size_t)E_ * FF_ * D_)      // 33554432 elements per weight tensor

// ------------------------- device scratch ----------------------------------
__device__ __align__(16) __half g_Wg16[WCOUNT];
__device__ __align__(16) __half g_Wu16[WCOUNT];
__device__ __align__(16) __half g_Wd16[WCOUNT];
__device__ __align__(16) __half g_H16[(size_t)PADROWS * FF_];
__device__ __align__(16) __half g_Xg16[(size_t)PADROWS * D_];
__device__ __align__(16) __half g_O16[(size_t)PADROWS * D_];
__device__ int   g_topk_idx[NP];
__device__ float g_topk_w[NP];
__device__ float g_probsum[E_];
__device__ int   g_count[E_];
__device__ float g_lse2;
__device__ int   g_offset[E_ + 1];
__device__ int   g_cursor[E_];
__device__ int   g_pair_token[PADROWS];
__device__ int   g_token_pos[NP];
__device__ int   g_tile_expert[NTILES];

// ------------------------- helpers -----------------------------------------
__device__ __forceinline__ uint32_t smem_u32(const void* p) {
    uint32_t a;
    asm("{ .reg .u64 t; cvta.to.shared.u64 t, %1; cvt.u32.u64 %0, t; }"
        : "=r"(a) : "l"(p));
    return a;
}
__device__ __forceinline__ void cp_async16(uint32_t s, const void* g) {
    asm volatile("cp.async.cg.shared.global [%0], [%1], 16;" :: "r"(s), "l"(g));
}
#define CP_COMMIT() asm volatile("cp.async.commit_group;" ::: "memory")
#define CP_WAIT(n)  asm volatile("cp.async.wait_group %0;" :: "n"(n) : "memory")

// D += A(16x16) * B(16x8)  fp16 in, fp32 accum
__device__ __forceinline__ void mma16(float* c, const uint32_t* a, uint32_t b0, uint32_t b1) {
    asm volatile(
        "mma.sync.aligned.m16n8k16.row.col.f32.f16.f16.f32 "
        "{%0,%1,%2,%3}, {%4,%5,%6,%7}, {%8,%9}, {%0,%1,%2,%3};"
        : "+f"(c[0]), "+f"(c[1]), "+f"(c[2]), "+f"(c[3])
        : "r"(a[0]), "r"(a[1]), "r"(a[2]), "r"(a[3]), "r"(b0), "r"(b1));
}

// ------------------------- init ---------------------------------------------
__global__ void init_kernel() {
    int i = blockIdx.x * blockDim.x + threadIdx.x;
    if (i < PADROWS) g_pair_token[i] = -1;
    if (i < E_) { g_count[i] = 0; g_probsum[i] = 0.f; g_cursor[i] = 0; }
    if (i == 0) g_lse2 = 0.f;
}

// ------------------------- fp32 -> fp16 conversions --------------------------
__global__ void convert_gu_kernel(const float* __restrict__ wg,
                                  const float* __restrict__ wu) {
    const size_t n4 = WCOUNT / 4;
    size_t stride = (size_t)gridDim.x * blockDim.x;
    for (size_t i = blockIdx.x * blockDim.x + threadIdx.x; i < 2 * n4; i += stride) {
        const float* src; __half* dst; size_t j;
        if (i < n4) { src = wg; dst = g_Wg16; j = i; }
        else        { src = wu; dst = g_Wu16; j = i - n4; }
        float4 v = __ldcs((const float4*)(src + j * 4));
        __half2 p0 = __floats2half2_rn(v.x, v.y);
        __half2 p1 = __floats2half2_rn(v.z, v.w);
        uint2 u;
        u.x = *(uint32_t*)&p0;
        u.y = *(uint32_t*)&p1;
        *(uint2*)(dst + j * 4) = u;
    }
}
__global__ void convert_d_kernel(const float* __restrict__ wd) {
    const size_t n4 = WCOUNT / 4;
    size_t stride = (size_t)gridDim.x * blockDim.x;
    for (size_t i = blockIdx.x * blockDim.x + threadIdx.x; i < n4; i += stride) {
        float4 v = __ldcs((const float4*)(wd + i * 4));
        __half2 p0 = __floats2half2_rn(v.x, v.y);
        __half2 p1 = __floats2half2_rn(v.z, v.w);
        uint2 u;
        u.x = *(uint32_t*)&p0;
        u.y = *(uint32_t*)&p1;
        *(uint2*)(g_Wd16 + i * 4) = u;
    }
}

// ------------------------- router (fp32, smem-cached gate_W) -----------------
__global__ __launch_bounds__(256) void router_kernel(const float* __restrict__ x,
                                                     const float* __restrict__ gw) {
    __shared__ float4 s_gw[E_ * 256];     // 32KB
    __shared__ float s_p[E_];
    __shared__ int   s_c[E_];
    __shared__ float s_l;
    const int tid = threadIdx.x;
    if (tid < E_) { s_p[tid] = 0.f; s_c[tid] = 0; }
    if (tid == 0) s_l = 0.f;
    for (int i = tid; i < E_ * 256; i += 256) s_gw[i] = ((const float4*)gw)[i];
    __syncthreads();

    int warp = (blockIdx.x * blockDim.x + tid) >> 5;
    int lane = tid & 31;
    {
        const float4* xr = (const float4*)(x + (size_t)warp * D_);
        float acc[E_];
#pragma unroll
        for (int e = 0; e < E_; e++) acc[e] = 0.f;
#pragma unroll
        for (int it = 0; it < 8; it++) {
            int i4 = lane + it * 32;
            float4 xv = xr[i4];
#pragma unroll
            for (int e = 0; e < E_; e++) {
                float4 w4 = s_gw[e * 256 + i4];
                acc[e] += xv.x * w4.x + xv.y * w4.y + xv.z * w4.z + xv.w * w4.w;
            }
        }
#pragma unroll
        for (int e = 0; e < E_; e++)
#pragma unroll
            for (int o = 16; o; o >>= 1)
                acc[e] += __shfl_xor_sync(0xffffffffu, acc[e], o);

        if (lane == 0) {
            float mx = acc[0];
#pragma unroll
            for (int e = 1; e < E_; e++) mx = fmaxf(mx, acc[e]);
            float p[E_], se = 0.f;
#pragma unroll
            for (int e = 0; e < E_; e++) { p[e] = expf(acc[e] - mx); se += p[e]; }
            float lse = mx + logf(se);
            float inv = 1.f / se;
#pragma unroll
            for (int e = 0; e < E_; e++) p[e] *= inv;

            int i1 = 0;
#pragma unroll
            for (int e = 1; e < E_; e++) if (p[e] > p[i1]) i1 = e;
            int i2 = (i1 == 0) ? 1 : 0;
#pragma unroll
            for (int e = 0; e < E_; e++) if (e != i1 && p[e] > p[i2]) i2 = e;

            float s2 = p[i1] + p[i2] + 1e-6f;
            g_topk_idx[2 * warp]     = i1;
            g_topk_w[2 * warp]       = p[i1] / s2;
            g_topk_idx[2 * warp + 1] = i2;
            g_topk_w[2 * warp + 1]   = p[i2] / s2;

            atomicAdd(&s_c[i1], 1);
            atomicAdd(&s_c[i2], 1);
#pragma unroll
            for (int e = 0; e < E_; e++) atomicAdd(&s_p[e], p[e]);
            atomicAdd(&s_l, lse * lse);
        }
    }
    __syncthreads();
    if (tid < E_) {
        atomicAdd(&g_probsum[tid], s_p[tid]);
        atomicAdd(&g_count[tid],   s_c[tid]);
    }
    if (tid == 0) atomicAdd(&g_lse2, s_l);
}

// ------------------------- scatter (+ inline scan / tile map / aux) ---------
__global__ void scatter_kernel(float* __restrict__ d_out, int out_size) {
    int offs[E_ + 1];
    int off = 0;
#pragma unroll
    for (int e = 0; e < E_; e++) {
        offs[e] = off;
        off += ((g_count[e] + TILE - 1) / TILE) * TILE;
    }
    offs[E_] = off;

    int i = blockIdx.x * blockDim.x + threadIdx.x;
    if (i < NP) {
        int e   = g_topk_idx[i];
        int pos = offs[e] + atomicAdd(&g_cursor[e], 1);
        g_pair_token[pos] = i >> 1;
        g_token_pos[i]    = pos;
    }

    if (blockIdx.x == 0) {
        int t = threadIdx.x;
        if (t <= E_) g_offset[t] = offs[t];
        if (t < NTILES) {
            int r = t * TILE;
            int e = E_ - 1;
#pragma unroll
            for (int j = 0; j < E_; j++)
                if (r < offs[j + 1]) { e = j; break; }
            g_tile_expert[t] = e;
        }
        if (t == 0) {
            float lb = 0.f;
#pragma unroll
            for (int e = 0; e < E_; e++)
                lb += ((float)g_count[e] / (float)NP) * (g_probsum[e] / (float)NTOK);
            lb *= (float)E_;
            float z   = (g_lse2 / (float)NTOK) * 1e-3f;
            float aux = 0.01f * (lb + z);
            if (out_size > NTOK * D_) d_out[NTOK * D_] = aux;
        }
    }
}

// ------------------------- gather x rows -> fp16 ----------------------------
__global__ void gather_kernel(const float* __restrict__ x) {
    int r = blockIdx.x;
    if (r >= g_offset[E_]) return;
    int tok = g_pair_token[r];
    uint2 u = make_uint2(0u, 0u);
    if (tok >= 0) {
        float4 v = *(const float4*)(x + (size_t)tok * D_ + threadIdx.x * 4);
        __half2 p0 = __floats2half2_rn(v.x, v.y);
        __half2 p1 = __floats2half2_rn(v.z, v.w);
        u.x = *(uint32_t*)&p0;
        u.y = *(uint32_t*)&p1;
    }
    *(uint2*)(g_Xg16 + (size_t)r * D_ + threadIdx.x * 4) = u;
}

// ------------------------- GEMM1: H = silu(X Wg^T) * (X Wu^T) ---------------
// Single-pass fused, block tile 128(M)x64(N) over BOTH gate and up.
// 256 threads, warp tile 64(M)x16(N) per tensor, 3-stage cp.async, occ 2.
__global__ __launch_bounds__(256, 2) void gemm1_kernel() {
    if ((int)blockIdx.y * 128 >= g_offset[E_]) return;   // skip empty tiles
    extern __shared__ __align__(16) char smc[];
    const uint32_t smb = smem_u32(smc);
    const int tid = threadIdx.x, wid = tid >> 5, lane = tid & 31;
    const int wm = wid & 1, wn = wid >> 1;               // 2 x 4 warps
    const int gq = lane >> 2, tq = lane & 3;
    const int bx = blockIdx.x, by = blockIdx.y;          // bx: 64-col tile of FF
    const int e = g_tile_expert[by];
    const __half* A0  = g_Xg16 + (size_t)by * 128 * D_;
    const __half* Bg0 = g_Wg16 + (size_t)e * FF_ * D_ + (size_t)bx * 64 * D_;
    const __half* Bu0 = g_Wu16 + (size_t)e * FF_ * D_ + (size_t)bx * 64 * D_;

    float cg[4][2][4], cu[4][2][4];
#pragma unroll
    for (int m = 0; m < 4; m++)
#pragma unroll
        for (int j = 0; j < 2; j++)
#pragma unroll
            for (int q = 0; q < 4; q++) { cg[m][j][q] = 0.f; cu[m][j][q] = 0.f; }

    const int C = D_ / KC;   // 16

#define G1_LOAD(c_)                                                            \
    do {                                                                       \
        uint32_t sb_ = smb + ((c_) % STAGES) * G1_STAGE_B;                     \
        const __half* a_  = A0  + (c_) * KC;                                   \
        const __half* bg_ = Bg0 + (c_) * KC;                                   \
        const __half* bu_ = Bu0 + (c_) * KC;                                   \
        _Pragma("unroll")                                                      \
        for (int i_ = 0; i_ < 4; i_++) {           /* A: 128 rows */           \
            int idx_ = i_ * 256 + tid;                                         \
            int r_ = idx_ >> 3, ch_ = idx_ & 7;                                \
            uint32_t off_ = (uint32_t)(r_ * RSB + ch_ * 16);                   \
            cp_async16(sb_ + off_, a_ + (size_t)r_ * D_ + ch_ * 8);            \
        }                                                                      \
        _Pragma("unroll")                                                      \
        for (int i_ = 0; i_ < 2; i_++) {           /* Bg/Bu: 64 rows */        \
            int idx_ = i_ * 256 + tid;                                         \
            int r_ = idx_ >> 3, ch_ = idx_ & 7;                                \
            uint32_t off_ = (uint32_t)(r_ * RSB + ch_ * 16);                   \
            cp_async16(sb_ + TILE_B + off_,                                    \
                       bg_ + (size_t)r_ * D_ + ch_ * 8);                       \
            cp_async16(sb_ + TILE_B + HTILE_B + off_,                          \
                       bu_ + (size_t)r_ * D_ + ch_ * 8);                       \
        }                                                                      \
        CP_COMMIT();                                                           \
    } while (0)

    G1_LOAD(0);
    G1_LOAD(1);

    for (int c = 0; c < C; c++) {
        if (c + 2 < C) CP_WAIT(1); else CP_WAIT(0);
        __syncthreads();
        if (c + 2 < C) G1_LOAD(c + 2);

        const char* As = smc + (c % STAGES) * G1_STAGE_B;
        const char* Gs = As + TILE_B;
        const char* Us = Gs + HTILE_B;
#pragma unroll
        for (int ks = 0; ks < 4; ks++) {
            const int kb = ks * 32;
            uint32_t a[4][4];
#pragma unroll
            for (int m = 0; m < 4; m++) {
                int r0 = wm * 64 + m * 16 + gq;
                a[m][0] = *(const uint32_t*)(As + r0 * RSB + kb + 4 * tq);
                a[m][1] = *(const uint32_t*)(As + (r0 + 8) * RSB + kb + 4 * tq);
                a[m][2] = *(const uint32_t*)(As + r0 * RSB + kb + 16 + 4 * tq);
                a[m][3] = *(const uint32_t*)(As + (r0 + 8) * RSB + kb + 16 + 4 * tq);
            }
#pragma unroll
            for (int j = 0; j < 2; j++) {
                int n = wn * 16 + j * 8 + gq;
                uint32_t g0 = *(const uint32_t*)(Gs + n * RSB + kb + 4 * tq);
                uint32_t g1 = *(const uint32_t*)(Gs + n * RSB + kb + 16 + 4 * tq);
#pragma unroll
                for (int m = 0; m < 4; m++) mma16(cg[m][j], a[m], g0, g1);
                uint32_t u0 = *(const uint32_t*)(Us + n * RSB + kb + 4 * tq);
                uint32_t u1 = *(const uint32_t*)(Us + n * RSB + kb + 16 + 4 * tq);
#pragma unroll
                for (int m = 0; m < 4; m++) mma16(cu[m][j], a[m], u0, u1);
            }
        }
    }

    // epilogue: h = silu(g) * u  (fp32, fused) -> fp16 H
#pragma unroll
    for (int m = 0; m < 4; m++) {
        int row = by * 128 + wm * 64 + m * 16 + gq;
#pragma unroll
        for (int j = 0; j < 2; j++) {
            int col = bx * 64 + wn * 16 + j * 8 + 2 * tq;
            float gg0 = cg[m][j][0], gg1 = cg[m][j][1];
            float gg2 = cg[m][j][2], gg3 = cg[m][j][3];
            float h0 = gg0 / (1.f + __expf(-gg0)) * cu[m][j][0];
            float h1 = gg1 / (1.f + __expf(-gg1)) * cu[m][j][1];
            float h2 = gg2 / (1.f + __expf(-gg2)) * cu[m][j][2];
            float h3 = gg3 / (1.f + __expf(-gg3)) * cu[m][j][3];
            *(__half2*)&g_H16[(size_t)row * FF_ + col]       = __floats2half2_rn(h0, h1);
            *(__half2*)&g_H16[(size_t)(row + 8) * FF_ + col] = __floats2half2_rn(h2, h3);
        }
    }
}

// ------------------------- GEMM2: O = H Wd^T (fp16 out, occ 2) --------------
__global__ __launch_bounds__(256, 2) void gemm2_kernel() {
    if ((int)blockIdx.y * 128 >= g_offset[E_]) return;   // skip empty tiles
    extern __shared__ __align__(16) char smc[];
    const uint32_t smb = smem_u32(smc);
    const int tid = threadIdx.x, wid = tid >> 5, lane = tid & 31;
    const int wm = wid & 1, wn = wid >> 1;
    const int gq = lane >> 2, tq = lane & 3;
    const int bx = blockIdx.x, by = blockIdx.y;
    const int e = g_tile_expert[by];
    const __half* A0 = g_H16 + (size_t)by * 128 * FF_;
    const __half* B0 = g_Wd16 + (size_t)e * D_ * FF_ + (size_t)bx * 128 * FF_;

    float cc[4][4][4];
#pragma unroll
    for (int m = 0; m < 4; m++)
#pragma unroll
        for (int j = 0; j < 4; j++)
#pragma unroll
            for (int q = 0; q < 4; q++) cc[m][j][q] = 0.f;

    const int C = FF_ / KC;   // 64

#define G2_LOAD(c_)                                                            \
    do {                                                                       \
        uint32_t sb_ = smb + ((c_) % STAGES) * (2 * TILE_B);                   \
        const __half* a_ = A0 + (c_) * KC;                                     \
        const __half* b_ = B0 + (c_) * KC;                                     \
        _Pragma("unroll")                                                      \
        for (int i_ = 0; i_ < 4; i_++) {                                       \
            int idx_ = i_ * 256 + tid;                                         \
            int r_ = idx_ >> 3, ch_ = idx_ & 7;                                \
            uint32_t off_ = (uint32_t)(r_ * RSB + ch_ * 16);                   \
            cp_async16(sb_ + off_,          a_ + (size_t)r_ * FF_ + ch_ * 8);  \
            cp_async16(sb_ + TILE_B + off_, b_ + (size_t)r_ * FF_ + ch_ * 8);  \
        }                                                                      \
        CP_COMMIT();                                                           \
    } while (0)

    G2_LOAD(0);
    G2_LOAD(1);

    for (int c = 0; c < C; c++) {
        if (c + 2 < C) CP_WAIT(1); else CP_WAIT(0);
        __syncthreads();
        if (c + 2 < C) G2_LOAD(c + 2);

        const char* As = smc + (c % STAGES) * (2 * TILE_B);
        const char* Bs = As + TILE_B;
#pragma unroll
        for (int ks = 0; ks < 4; ks++) {
            const int kb = ks * 32;
            uint32_t a[4][4];
#pragma unroll
            for (int m = 0; m < 4; m++) {
                int r0 = wm * 64 + m * 16 + gq;
                a[m][0] = *(const uint32_t*)(As + r0 * RSB + kb + 4 * tq);
                a[m][1] = *(const uint32_t*)(As + (r0 + 8) * RSB + kb + 4 * tq);
                a[m][2] = *(const uint32_t*)(As + r0 * RSB + kb + 16 + 4 * tq);
                a[m][3] = *(const uint32_t*)(As + (r0 + 8) * RSB + kb + 16 + 4 * tq);
            }
#pragma unroll
            for (int j = 0; j < 4; j++) {
                int n = wn * 32 + j * 8 + gq;
                uint32_t b0 = *(const uint32_t*)(Bs + n * RSB + kb + 4 * tq);
                uint32_t b1 = *(const uint32_t*)(Bs + n * RSB + kb + 16 + 4 * tq);
#pragma unroll
                for (int m = 0; m < 4; m++) mma16(cc[m][j], a[m], b0, b1);
            }
        }
    }

#pragma unroll
    for (int m = 0; m < 4; m++) {
        int row = by * 128 + wm * 64 + m * 16 + gq;
#pragma unroll
        for (int j = 0; j < 4; j++) {
            int col = bx * 128 + wn * 32 + j * 8 + 2 * tq;
            *(__half2*)&g_O16[(size_t)row * D_ + col] =
                __floats2half2_rn(cc[m][j][0], cc[m][j][1]);
            *(__half2*)&g_O16[(size_t)(row + 8) * D_ + col] =
                __floats2half2_rn(cc[m][j][2], cc[m][j][3]);
        }
    }
}

// ------------------------- combine + residual + LayerNorm -------------------
__global__ void combine_ln_kernel(const float* __restrict__ x,
                                  const float* __restrict__ gamma,
                                  const float* __restrict__ beta,
                                  float* __restrict__ out) {
    int t  = blockIdx.x;
    int p0 = g_token_pos[2 * t];
    int p1 = g_token_pos[2 * t + 1];
    float w0 = g_topk_w[2 * t];
    float w1 = g_topk_w[2 * t + 1];
    const float*  xr = x     + (size_t)t  * D_;
    const __half* o0 = g_O16 + (size_t)p0 * D_;
    const __half* o1 = g_O16 + (size_t)p1 * D_;

    int d4 = threadIdx.x * 4;
    float4 xv = *(const float4*)(xr + d4);
    uint2 u0 = *(const uint2*)(o0 + d4);
    uint2 u1 = *(const uint2*)(o1 + d4);
    __half2 a0 = *(__half2*)&u0.x, a1 = *(__half2*)&u0.y;
    __half2 b0 = *(__half2*)&u1.x, b1 = *(__half2*)&u1.y;

    float v[4];
    v[0] = xv.x + w0 * __low2float(a0)  + w1 * __low2float(b0);
    v[1] = xv.y + w0 * __high2float(a0) + w1 * __high2float(b0);
    v[2] = xv.z + w0 * __low2float(a1)  + w1 * __low2float(b1);
    v[3] = xv.w + w0 * __high2float(a1) + w1 * __high2float(b1);

    float s = v[0] + v[1] + v[2] + v[3];
    float s2 = v[0] * v[0] + v[1] * v[1] + v[2] * v[2] + v[3] * v[3];
#pragma unroll
    for (int o = 16; o; o >>= 1) {
        s  += __shfl_xor_sync(0xffffffffu, s, o);
        s2 += __shfl_xor_sync(0xffffffffu, s2, o);
    }
    __shared__ float rs[8], rs2[8];
    __shared__ float s_mu, s_rstd;
    int wid = threadIdx.x >> 5, lane = threadIdx.x & 31;
    if (lane == 0) { rs[wid] = s; rs2[wid] = s2; }
    __syncthreads();
    if (threadIdx.x == 0) {
        float S = 0.f, S2 = 0.f;
#pragma unroll
        for (int w = 0; w < 8; w++) { S += rs[w]; S2 += rs2[w]; }
        float mu  = S / (float)D_;
        float var = S2 / (float)D_ - mu * mu;
        s_mu   = mu;
        s_rstd = rsqrtf(var + 1e-5f);
    }
    __syncthreads();
    float mu = s_mu, rstd = s_rstd;
    float4 gv = *(const float4*)(gamma + d4);
    float4 bv = *(const float4*)(beta + d4);
    float4 ov;
    ov.x = (v[0] - mu) * rstd * gv.x + bv.x;
    ov.y = (v[1] - mu) * rstd * gv.y + bv.y;
    ov.z = (v[2] - mu) * rstd * gv.z + bv.z;
    ov.w = (v[3] - mu) * rstd * gv.w + bv.w;
    *(float4*)(out + (size_t)t * D_ + d4) = ov;
}

// ------------------------- launch -------------------------------------------
extern "C" void kernel_launch(void* const* d_in, const int* in_sizes, int n_in,
                              void* d_out, int out_size) {
    const float* x     = (const float*)d_in[0];
    const float* gateW = (const float*)d_in[1];
    const float* Wg    = (const float*)d_in[2];
    const float* Wu    = (const float*)d_in[3];
    const float* Wd    = (const float*)d_in[4];
    const float* gamma = (const float*)d_in[5];
    const float* beta  = (const float*)d_in[6];
    float* out = (float*)d_out;

    static cudaStream_t s2 = nullptr;
    static cudaEvent_t evA = nullptr, evGU = nullptr, evD = nullptr;
    if (!s2) {
        cudaStreamCreateWithFlags(&s2, cudaStreamNonBlocking);
        cudaEventCreateWithFlags(&evA,  cudaEventDisableTiming);
        cudaEventCreateWithFlags(&evGU, cudaEventDisableTiming);
        cudaEventCreateWithFlags(&evD,  cudaEventDisableTiming);
    }

    cudaFuncSetAttribute((const void*)gemm1_kernel,
                         cudaFuncAttributeMaxDynamicSharedMemorySize, G1_SMEM);
    cudaFuncSetAttribute((const void*)gemm2_kernel,
                         cudaFuncAttributeMaxDynamicSharedMemorySize, G2_SMEM);

    // Fork: weight conversion on s2 (gate+up first, then down).
    cudaEventRecord(evA, 0);
    cudaStreamWaitEvent(s2, evA, 0);
    convert_gu_kernel<<<2048, 256, 0, s2>>>(Wg, Wu);
    cudaEventRecord(evGU, s2);
    convert_d_kernel<<<2048, 256, 0, s2>>>(Wd);
    cudaEventRecord(evD, s2);

    // Routing pipeline on main stream.
    init_kernel<<<(PADROWS + 255) / 256, 256>>>();
    router_kernel<<<NTOK / 8, 256>>>(x, gateW);
    scatter_kernel<<<(NP + 255) / 256, 256>>>(out, out_size);
    gather_kernel<<<PADROWS, 256>>>(x);

    // GEMM1 needs only gate+up weights; GEMM2 also needs down weights.
    cudaStreamWaitEvent(0, evGU, 0);
    gemm1_kernel<<<dim3(FF_ / 64, NTILES), 256, G1_SMEM>>>();
    cudaStreamWaitEvent(0, evD, 0);
    gemm2_kernel<<<dim3(D_ / 128, NTILES), 256, G2_SMEM>>>();

    combine_ln_kernel<<<NTOK, 256>>>(x, gamma, beta, out);
}